// round 13
// baseline (speedup 1.0000x reference)
#include <cuda_runtime.h>

// Neural 2D min-sum LDPC decoder, (3,6)-regular layered graph.
// One CTA per codeword (TPB=1024, 1 CTA/SM). Edge state msg[l*NV+v] plus a
// 4th smem plane holding the channel LLRs (total 128KB) resident for all T
// iterations. In-place check/variable updates (per layer each variable is in
// exactly one check). Check c, layer l owns edges e = l*NV + 2c + {0,1}.
//
// R11 (2nd resubmission after broker failures): maximum-MLP check phase — ALL
// 4 checks' 24 random LDS are issued before any minsum/store (disjoint
// addresses across checks, so reordering is safe). The llr plane in smem frees
// the 8 registers this needs. Phase model: 2 random smem ops per edge per
// iteration is the irreducible minimum; the lever is L1 utilization (80->~90%).

#define NV 8192
#define MC 4096
#define NL 3
#define TPB 1024
#define VPT (NV / TPB)    // 8 strided variables per thread
#define CPT (MC / TPB)    // 4 checks per thread (strided)
#define SMEM_BYTES ((NL + 1) * NV * 4)   // 3 msg planes + llr plane = 128KB

// Multiset 2-min min-sum core on sign-magnitude bits; exactly reproduces the
// reference min1/min2/argmin + sign-product semantics (incl. ties and zeros).
// (validated rel_err==0.0 in R5-R10 benches)
__device__ __forceinline__ void minsum6(const unsigned u[6], float bt, unsigned res[6])
{
    unsigned a0 = u[0] & 0x7fffffffu, a1 = u[1] & 0x7fffffffu;
    unsigned a2 = u[2] & 0x7fffffffu, a3 = u[3] & 0x7fffffffu;
    unsigned a4 = u[4] & 0x7fffffffu, a5 = u[5] & 0x7fffffffu;
    unsigned xs = (u[0] ^ u[1]) ^ (u[2] ^ u[3]) ^ (u[4] ^ u[5]);

    // nonnegative float bits order as unsigned ints
    unsigned lo01 = min(a0, a1), hi01 = max(a0, a1);
    unsigned lo23 = min(a2, a3), hi23 = max(a2, a3);
    unsigned lo45 = min(a4, a5), hi45 = max(a4, a5);
    unsigned m1a  = min(lo01, lo23);
    unsigned m2a  = min(max(lo01, lo23), min(hi01, hi23));
    unsigned m1   = min(m1a, lo45);
    unsigned m2   = min(max(m1a, lo45), min(m2a, hi45));
    m2 = (m1 == 0u) ? 0u : m2;   // exact zero => sign product 0 => all c2v = 0

    unsigned b1 = __float_as_uint(bt * __uint_as_float(m1));
    unsigned b2 = __float_as_uint(bt * __uint_as_float(m2));

    unsigned as[6] = {a0, a1, a2, a3, a4, a5};
#pragma unroll
    for (int p = 0; p < 6; p++) {
        unsigned mag = (as[p] == m1) ? b2 : b1;          // ties => b1==b2
        res[p] = mag ^ ((xs ^ u[p]) & 0x80000000u);
    }
}

__global__ __launch_bounds__(TPB, 1)
void bp_kernel(const float* __restrict__ llr,
               const int*   __restrict__ edge_v,
               const float* __restrict__ beta,
               const float* __restrict__ alpha,
               float* __restrict__ out_f,
               int*   __restrict__ out_i,
               int B, int T, int mode)
{
    extern __shared__ float msg[];           // [NL*NV] messages + [NV] llr
    float* lsm = msg + NL * NV;              // llr plane

    const int tid = threadIdx.x;

    // Register-resident check->var table (graph fixed across codewords/iters).
    unsigned pk[CPT][NL];
#pragma unroll
    for (int k = 0; k < CPT; k++) {
        int c = tid + k * TPB;
#pragma unroll
        for (int l = 0; l < NL; l++) {
            unsigned v0 = (unsigned)edge_v[l * NV + 2 * c];
            unsigned v1 = (unsigned)edge_v[l * NV + 2 * c + 1];
            pk[k][l] = v0 | (v1 << 16);
        }
    }

    for (int cw = blockIdx.x; cw < B; cw += gridDim.x) {
        // Channel LLRs -> llr plane + v2c init (coalesced LDG + scalar STS).
#pragma unroll
        for (int k = 0; k < VPT; k++) {
            int v = tid + k * TPB;
            float x = __ldg(llr + (size_t)cw * NV + v);
            lsm[v]          = x;
            msg[v]          = x;
            msg[NV + v]     = x;
            msg[2 * NV + v] = x;
        }
        __syncthreads();

        for (int t = 0; t < T; t++) {
            float bt = __ldg(beta + t);
            float at = __ldg(alpha + t);

            // ---------- check phase: v2c -> c2v, all loads up front ----------
            unsigned u[CPT][6];
#pragma unroll
            for (int k = 0; k < CPT; k++)
#pragma unroll
                for (int l = 0; l < NL; l++) {
                    u[k][2 * l]     = __float_as_uint(msg[l * NV + (int)(pk[k][l] & 0xFFFFu)]);
                    u[k][2 * l + 1] = __float_as_uint(msg[l * NV + (int)(pk[k][l] >> 16)]);
                }
#pragma unroll
            for (int k = 0; k < CPT; k++) {
                unsigned r[6];
                minsum6(u[k], bt, r);
#pragma unroll
                for (int l = 0; l < NL; l++) {
                    msg[l * NV + (int)(pk[k][l] & 0xFFFFu)] = __uint_as_float(r[2 * l]);
                    msg[l * NV + (int)(pk[k][l] >> 16)]     = __uint_as_float(r[2 * l + 1]);
                }
            }
            __syncthreads();

            // ---------- variable phase: c2v -> v2c, 2-stride batches ----------
            if (t + 1 < T) {
#pragma unroll
                for (int k = 0; k < VPT; k += 2) {
                    int va = tid + k * TPB;          // coalesced, conflict-free
                    int vb = tid + (k + 1) * TPB;
                    float a0 = msg[va], a1 = msg[NV + va], a2 = msg[2 * NV + va];
                    float b0 = msg[vb], b1 = msg[NV + vb], b2 = msg[2 * NV + vb];
                    float ba = lsm[va], bb = lsm[vb];
                    float sa = a0 + a1 + a2;
                    float sb = b0 + b1 + b2;
                    msg[va]          = ba + at * (sa - a0);
                    msg[NV + va]     = ba + at * (sa - a1);
                    msg[2 * NV + va] = ba + at * (sa - a2);
                    msg[vb]          = bb + at * (sb - b0);
                    msg[NV + vb]     = bb + at * (sb - b1);
                    msg[2 * NV + vb] = bb + at * (sb - b2);
                }
                __syncthreads();
            }
        }

        // ---------- posterior + hard decision ----------
#pragma unroll
        for (int k = 0; k < VPT; k++) {
            int v = tid + k * TPB;
            float post = lsm[v] + (msg[v] + msg[NV + v] + msg[2 * NV + v]);
            size_t idx = (size_t)cw * NV + v;
            if (mode) {
                // out = [decoded_bits (as f32 0/1) | posterior], each [B,N]
                out_f[idx] = (post < 0.0f) ? 1.0f : 0.0f;
                out_f[(size_t)B * NV + idx] = post;
            } else {
                out_i[idx] = (post < 0.0f) ? 1 : 0;
            }
        }
        __syncthreads();   // protect smem before next codeword reuses it
    }
}

extern "C" void kernel_launch(void* const* d_in, const int* in_sizes, int n_in,
                              void* d_out, int out_size) {
    // metadata order: llr [B,N] f32, edge_v [E] i32, edge_c [E] i32 (implicit),
    // beta [T] f32, alpha [T] f32
    const float* llr    = (const float*)d_in[0];
    const int*   edge_v = (const int*)  d_in[1];
    const float* beta   = (const float*)d_in[3];
    const float* alpha  = (const float*)d_in[4];

    int B = in_sizes[0] / NV;
    int T = in_sizes[3];
    int mode = (out_size >= 2 * B * NV) ? 1 : 0;

    cudaFuncSetAttribute((const void*)bp_kernel,
                         cudaFuncAttributeMaxDynamicSharedMemorySize, SMEM_BYTES);
    bp_kernel<<<B, TPB, SMEM_BYTES>>>(llr, edge_v, beta, alpha,
                                      (float*)d_out, (int*)d_out, B, T, mode);
}